// round 3
// baseline (speedup 1.0000x reference)
#include <cuda_runtime.h>
#include <math.h>

#define Nx   256
#define BN   2048      // 8*256

// ---------------- scratch ----------------
__device__ float g_A [BN*128];   // h @ Wm1[0:128]
__device__ float g_Bm[BN*128];   // h @ Wm1[128:256]
__device__ float g_as[BN];
__device__ float g_bs[BN];
__device__ float g_M [128*128];  // Wm2 @ Wu_bot
__device__ float g_vb[128];      // bm2 @ Wu_bot + bu

typedef unsigned long long u64;

__device__ __forceinline__ u64 dup2(float a) {
    u64 r; unsigned au = __float_as_uint(a);
    asm("mov.b64 %0, {%1, %1};" : "=l"(r) : "r"(au));
    return r;
}
__device__ __forceinline__ void fma2(u64& acc, u64 a, u64 b) {
    asm("fma.rn.f32x2 %0, %1, %2, %0;" : "+l"(acc) : "l"(a), "l"(b));
}
__device__ __forceinline__ float2 unpk(u64 v) {
    unsigned lo, hi;
    asm("mov.b64 {%0, %1}, %2;" : "=r"(lo), "=r"(hi) : "l"(v));
    return make_float2(__uint_as_float(lo), __uint_as_float(hi));
}

// =======================================================================
// Stage 1: C[2048,256]=h@Wm1 (-> g_A|g_Bm), M=Wm2@Wu_bot, dots, vb
// grid 141, block 256, dyn smem 69632
// =======================================================================
#define S1_SMEM (2*128*68*4)

__global__ void __launch_bounds__(256) k_stage1(
    const float* __restrict__ h,   const float* __restrict__ Wm1,
    const float* __restrict__ Wa,  const float* __restrict__ Wm2,
    const float* __restrict__ bm2, const float* __restrict__ Wu,
    const float* __restrict__ bu)
{
    extern __shared__ float sm[];
    const int bid = blockIdx.x;
    const int t   = threadIdx.x;

    if (bid < 132) {
        float* At = sm;              // [128][68]  (k-major, transposed A)
        float* Ws = sm + 128*68;     // [128][68]  (k-major W)
        const float *A, *W;
        float* dst;
        int row0, col0;
        if (bid < 128) {
            int mt = bid >> 2, nt = bid & 3;
            row0 = mt * 64;
            A = h;
            W = Wm1 + (nt >= 2 ? 128*128 : 0);
            col0 = (nt & 1) * 64;
            dst = (nt >= 2) ? g_Bm : g_A;
        } else {
            int bb = bid - 128;
            row0 = (bb >> 1) * 64;
            A = Wm2; W = Wu + 128*128;
            col0 = (bb & 1) * 64;
            dst = g_M;
        }
        // load A tile 64x128 -> transposed smem
#pragma unroll
        for (int n = 0; n < 8; n++) {
            int l = t + n*256;            // 0..2047 quads
            int r = l >> 5, kq = (l & 31) * 4;
            float4 v = *(const float4*)&A[(row0 + r)*128 + kq];
            At[(kq+0)*68 + r] = v.x; At[(kq+1)*68 + r] = v.y;
            At[(kq+2)*68 + r] = v.z; At[(kq+3)*68 + r] = v.w;
        }
        // load W tile 128x64
#pragma unroll
        for (int n = 0; n < 8; n++) {
            int l = t + n*256;
            int wk = l >> 4, wn = (l & 15) * 4;
            *(float4*)&Ws[wk*68 + wn] = *(const float4*)&W[wk*128 + col0 + wn];
        }
        __syncthreads();

        const int ty = t >> 4, tx = t & 15;
        u64 acc[4][2];
#pragma unroll
        for (int r = 0; r < 4; r++) { acc[r][0] = 0ull; acc[r][1] = 0ull; }

#pragma unroll 8
        for (int k = 0; k < 128; k++) {
            float4 a4 = *(const float4*)&At[k*68 + ty*4];
            ulonglong2 bb = *(const ulonglong2*)&Ws[k*68 + tx*4];
            u64 aa;
            aa = dup2(a4.x); fma2(acc[0][0], aa, bb.x); fma2(acc[0][1], aa, bb.y);
            aa = dup2(a4.y); fma2(acc[1][0], aa, bb.x); fma2(acc[1][1], aa, bb.y);
            aa = dup2(a4.z); fma2(acc[2][0], aa, bb.x); fma2(acc[2][1], aa, bb.y);
            aa = dup2(a4.w); fma2(acc[3][0], aa, bb.x); fma2(acc[3][1], aa, bb.y);
        }
#pragma unroll
        for (int r = 0; r < 4; r++) {
            float2 p = unpk(acc[r][0]), q = unpk(acc[r][1]);
            *(float4*)&dst[(row0 + ty*4 + r)*128 + col0 + tx*4] =
                make_float4(p.x, p.y, q.x, q.y);
        }

    } else if (bid < 140) {
        float* was = sm;   // 257 floats
        for (int k = t; k < 257; k += 256) was[k] = Wa[k];
        __syncthreads();
        const int wrp = t >> 5, lane = t & 31;
        const int rowbase = (bid - 132) * 256 + wrp * 32;
        float4 wa1 = *(const float4*)&was[lane*4];
        float4 wa2 = *(const float4*)&was[128 + lane*4];
        for (int rr = 0; rr < 32; rr++) {
            int row = rowbase + rr;
            float4 hv = *(const float4*)&h[row*128 + lane*4];
            float sa = hv.x*wa1.x + hv.y*wa1.y + hv.z*wa1.z + hv.w*wa1.w;
            float sb = hv.x*wa2.x + hv.y*wa2.y + hv.z*wa2.z + hv.w*wa2.w;
#pragma unroll
            for (int o = 16; o; o >>= 1) {
                sa += __shfl_xor_sync(0xffffffffu, sa, o);
                sb += __shfl_xor_sync(0xffffffffu, sb, o);
            }
            if (lane == 0) { g_as[row] = sa; g_bs[row] = sb; }
        }
    } else {
        if (t < 128) {
            float acc = bu[t];
#pragma unroll 8
            for (int k = 0; k < 128; k++)
                acc = fmaf(bm2[k], Wu[(128 + k)*128 + t], acc);
            g_vb[t] = acc;
        }
    }
}

// =======================================================================
// k_pair: softmax + weighted relu aggregation + FUSED output GEMM
// grid (16,8), block 512
// smem: Bsh 32768 | dyn 16384 (dw -> part -> hS) | Ash 2048 | bssh 256 | csh 16
// =======================================================================
#define PAIR_SMEM ((32768 + 16384 + 2048 + 256 + 16) * 4)

__global__ void __launch_bounds__(512, 1) k_pair(
    const float* __restrict__ h,
    const float* __restrict__ dist, const int* __restrict__ adj,
    const float* __restrict__ Wm1,  const float* __restrict__ bm1,
    const float* __restrict__ Wa,   const float* __restrict__ ba,
    const float* __restrict__ Wu,
    float* __restrict__ out)
{
    extern __shared__ float sm[];
    float*  Bsh  = sm;                       // 256*128 (B tile / later Wcat)
    float*  dyn  = sm + 32768;               // 16384 floats
    float*  Ash  = sm + 32768 + 16384;       // 16*128 (A + bm1)
    float*  bssh = Ash + 2048;               // 256
    float*  csh  = bssh + 256;               // 16

    float4* dwsh = (float4*)dyn;             // phase1/2: 16*256 {d,d,w,w}
    u64*    part = (u64*)dyn;                // after: 16*8*64 partials
    float*  hSsh = dyn;                      // after: [16][256] = [h | S]

    const int t = threadIdx.x;
    const int b = blockIdx.y, i0 = blockIdx.x * 16;
    const int lane = t & 31, wrp = t >> 5;

    // ---- fills
    {
        const float4* src = (const float4*)(g_Bm + (long)b*Nx*128);
        float4* d4 = (float4*)Bsh;
#pragma unroll
        for (int k = 0; k < 16; k++) d4[t + k*512] = src[t + k*512];
    }
#pragma unroll
    for (int k = 0; k < 4; k++) {
        int idx = t + k*512;
        Ash[idx] = g_A[(long)(b*Nx + i0)*128 + idx] + bm1[idx & 127];
    }
    if (t < 256) bssh[t] = g_bs[b*Nx + t];
    __syncthreads();

    // ---- phase 1: warp wrp -> i = i0 + wrp (softmax over j)
    const float wa_d = Wa[256];
    {
        const int ig = b*Nx + i0 + wrp;
        const float a_i = g_as[ig] + ba[0];
        float l[8], dv[8]; int mk[8];
#pragma unroll
        for (int jj = 0; jj < 8; jj++) {
            int j = jj*32 + lane;
            float d = dist[(long)ig*Nx + j];
            int   m = adj [(long)ig*Nx + j];
            float x = fmaf(d, wa_d, a_i + bssh[j]);
            x = (x >= 0.f) ? x : 0.2f * x;
            l[jj] = m ? x : -1e9f;
            dv[jj] = d; mk[jj] = m;
        }
        float mx = l[0];
#pragma unroll
        for (int jj = 1; jj < 8; jj++) mx = fmaxf(mx, l[jj]);
#pragma unroll
        for (int o = 16; o; o >>= 1) mx = fmaxf(mx, __shfl_xor_sync(0xffffffffu, mx, o));
        float sum = 0.f, cs = 0.f;
#pragma unroll
        for (int jj = 0; jj < 8; jj++) {
            float e = expf(l[jj] - mx);
            l[jj] = e; sum += e;
            cs += mk[jj] ? e : 0.f;
        }
#pragma unroll
        for (int o = 16; o; o >>= 1) {
            sum += __shfl_xor_sync(0xffffffffu, sum, o);
            cs  += __shfl_xor_sync(0xffffffffu, cs,  o);
        }
        float inv = 1.f / sum;
#pragma unroll
        for (int jj = 0; jj < 8; jj++) {
            int j = jj*32 + lane;
            float w = mk[jj] ? l[jj]*inv : 0.f;
            dwsh[wrp*256 + j] = make_float4(dv[jj], dv[jj], w, w);
        }
        if (lane == 0) csh[wrp] = cs * inv;
    }

    // ---- phase 2 registers
    const int cp = t & 63, q = t >> 6;
    u64 a2[16], acc2[16];
#pragma unroll
    for (int i = 0; i < 16; i++) {
        a2[i]   = *(const u64*)&Ash[i*128 + cp*2];
        acc2[i] = 0ull;
    }
    const u64 wd2 = *(const u64*)&Wm1[256*128 + cp*2];
    __syncthreads();

    // ---- phase 2: acc_i += w_ij * relu(A_ic + B_jc + d_ij*wd_c)
    const ulonglong2* dw2 = (const ulonglong2*)dwsh;
#pragma unroll 1
    for (int jj = 0; jj < 32; jj++) {
        int j = jj*8 + q;
        u64 b2 = *(const u64*)&Bsh[j*128 + cp*2];
        const ulonglong2* p = dw2 + j;
#pragma unroll
        for (int i = 0; i < 16; i++) {
            ulonglong2 dw = p[i*256];
            asm("{\n\t"
                ".reg .b64 tt;\n\t"
                ".reg .f32 lo, hi;\n\t"
                "add.rn.f32x2 tt, %1, %2;\n\t"
                "fma.rn.f32x2 tt, %3, %4, tt;\n\t"
                "mov.b64 {lo, hi}, tt;\n\t"
                "max.f32 lo, lo, 0f00000000;\n\t"
                "max.f32 hi, hi, 0f00000000;\n\t"
                "mov.b64 tt, {lo, hi};\n\t"
                "fma.rn.f32x2 %0, %5, tt, %0;\n\t"
                "}"
                : "+l"(acc2[i])
                : "l"(a2[i]), "l"(b2), "l"(dw.x), "l"(wd2), "l"(dw.y));
        }
    }
    __syncthreads();   // everyone done with Bsh(B) & dwsh

    // partials into dyn; meanwhile kick off Wcat = [Wu_top ; g_M] -> Bsh
#pragma unroll
    for (int i = 0; i < 16; i++) part[(i*8 + q)*64 + cp] = acc2[i];
#pragma unroll
    for (int n = 0; n < 16; n++) {
        int idx = t + n*512;            // 0..8191 quads
        int k = idx >> 5, c4 = (idx & 31) * 4;
        const float* src = (k < 128) ? &Wu[k*128 + c4]
                                     : &g_M[(k - 128)*128 + c4];
        *(float4*)&Bsh[k*128 + c4] = *(const float4*)src;
    }
    __syncthreads();

    // reduce 8 partials -> S regs (2 slots/thread)
    float2 sreg[2];
#pragma unroll
    for (int rep = 0; rep < 2; rep++) {
        int it = t + rep*512;
        int i = it >> 6, cpp = it & 63;
        float2 s = make_float2(0.f, 0.f);
#pragma unroll
        for (int qq = 0; qq < 8; qq++) {
            float2 v = unpk(part[(i*8 + qq)*64 + cpp]);
            s.x += v.x; s.y += v.y;
        }
        sreg[rep] = s;
    }
    __syncthreads();   // part fully read; dyn becomes hSsh

    // build hS = [h_i | S_i]  (16 x 256)
#pragma unroll
    for (int rep = 0; rep < 2; rep++) {
        int it = t + rep*512;
        int i = it >> 6, cpp = it & 63;
        *(float2*)&hSsh[i*256 + 128 + cpp*2] = sreg[rep];
    }
    {
        int i = t >> 5, c4 = (t & 31) * 4;
        *(float4*)&hSsh[i*256 + c4] =
            *(const float4*)&h[(long)(b*Nx + i0 + i)*128 + c4];
    }
    __syncthreads();

    // ---- fused epilogue GEMM: out[16,128] = hS @ Wcat, + c*vb, relu
    const int r = t >> 5, cq = t & 31;
    u64 oa0 = 0ull, oa1 = 0ull;
#pragma unroll 4
    for (int kq = 0; kq < 64; kq++) {
        float4 a4 = *(const float4*)&hSsh[r*256 + kq*4];
        u64 aa;
        ulonglong2 bb;
        bb = *(const ulonglong2*)&Bsh[(kq*4+0)*128 + cq*4];
        aa = dup2(a4.x); fma2(oa0, aa, bb.x); fma2(oa1, aa, bb.y);
        bb = *(const ulonglong2*)&Bsh[(kq*4+1)*128 + cq*4];
        aa = dup2(a4.y); fma2(oa0, aa, bb.x); fma2(oa1, aa, bb.y);
        bb = *(const ulonglong2*)&Bsh[(kq*4+2)*128 + cq*4];
        aa = dup2(a4.z); fma2(oa0, aa, bb.x); fma2(oa1, aa, bb.y);
        bb = *(const ulonglong2*)&Bsh[(kq*4+3)*128 + cq*4];
        aa = dup2(a4.w); fma2(oa0, aa, bb.x); fma2(oa1, aa, bb.y);
    }
    {
        float ci = csh[r];
        float4 vb4 = *(const float4*)&g_vb[cq*4];
        float2 p = unpk(oa0), qv = unpk(oa1);
        float4 o;
        o.x = fmaxf(fmaf(ci, vb4.x, p.x),  0.f);
        o.y = fmaxf(fmaf(ci, vb4.y, p.y),  0.f);
        o.z = fmaxf(fmaf(ci, vb4.z, qv.x), 0.f);
        o.w = fmaxf(fmaf(ci, vb4.w, qv.y), 0.f);
        *(float4*)&out[(long)(b*Nx + i0 + r)*128 + cq*4] = o;
    }
}

// =======================================================================
extern "C" void kernel_launch(void* const* d_in, const int* in_sizes, int n_in,
                              void* d_out, int out_size)
{
    const float* h    = (const float*)d_in[0];
    const int*   adj  = (const int*)  d_in[1];
    const float* dist = (const float*)d_in[2];
    const float* Wm1  = (const float*)d_in[3];
    const float* bm1  = (const float*)d_in[4];
    const float* Wm2  = (const float*)d_in[5];
    const float* bm2  = (const float*)d_in[6];
    const float* Wa   = (const float*)d_in[7];
    const float* ba   = (const float*)d_in[8];
    const float* Wu   = (const float*)d_in[9];
    const float* bu   = (const float*)d_in[10];
    float* out = (float*)d_out;

    cudaFuncSetAttribute(k_stage1, cudaFuncAttributeMaxDynamicSharedMemorySize,
                         S1_SMEM);
    cudaFuncSetAttribute(k_pair, cudaFuncAttributeMaxDynamicSharedMemorySize,
                         PAIR_SMEM);

    k_stage1<<<141, 256, S1_SMEM>>>(h, Wm1, Wa, Wm2, bm2, Wu, bu);
    k_pair  <<<dim3(16, 8), 512, PAIR_SMEM>>>(h, dist, adj, Wm1, bm1,
                                              Wa, ba, Wu, out);
}